// round 4
// baseline (speedup 1.0000x reference)
#include <cuda_runtime.h>
#include <cuda_bf16.h>
#include <cstdint>

// ============================ problem constants ============================
constexpr int M = 16384;
constexpr int N = 4096;
constexpr int K = 1024;

constexpr int TILE_M = 128;
constexpr int TILE_N = 256;
constexpr int TILE_K = 64;               // 64 bf16 = 128 B rows
constexpr int KSTEPS = K / TILE_K;       // 16
constexpr int STAGES = 4;
constexpr int M_TILES = M / TILE_M;      // 128
constexpr int N_TILES = N / TILE_N;      // 16
constexpr int THREADS = 256;             // 8 warps: 2(m) x 4(n), warp tile 64x64

// ============================ device scratch ===============================
__device__ __nv_bfloat16 g_xb[(size_t)M * K];          // 32 MB
__device__ __nv_bfloat16 g_wb[(size_t)N * K];          //  8 MB
__device__ float         g_part[(size_t)N_TILES * M];  //  1 MB

// ============================ smem layout (bytes) ==========================
constexpr int SM_BIAS   = 0;                         // 256 floats = 1024 B
constexpr int SM_ROWSUM = 1024;                      // 4 x 128 floats = 2048 B
constexpr int A_BYTES   = TILE_M * 128;              // 16384
constexpr int B_BYTES   = TILE_N * 128;              // 32768
constexpr int SM_A      = 4096;
constexpr int SM_B      = SM_A + STAGES * A_BYTES;   // 69632
constexpr int SMEM_TOTAL = SM_B + STAGES * B_BYTES;  // 200704 (196 KB)

// ============================ PTX helpers ==================================
__device__ __forceinline__ uint32_t smem_to_u32(const void* p) {
    uint32_t a;
    asm("{ .reg .u64 t; cvta.to.shared.u64 t, %1; cvt.u32.u64 %0, t; }"
        : "=r"(a) : "l"(p));
    return a;
}

__device__ __forceinline__ void cp_async16(uint32_t smem_dst, const void* gsrc) {
    asm volatile("cp.async.cg.shared.global [%0], [%1], 16;"
                 :: "r"(smem_dst), "l"(gsrc) : "memory");
}

__device__ __forceinline__ void cp_commit() {
    asm volatile("cp.async.commit_group;" ::: "memory");
}

__device__ __forceinline__ void ldmatrix_x4(uint32_t& r0, uint32_t& r1,
                                            uint32_t& r2, uint32_t& r3,
                                            uint32_t addr) {
    asm volatile("ldmatrix.sync.aligned.m8n8.x4.shared.b16 {%0,%1,%2,%3}, [%4];"
                 : "=r"(r0), "=r"(r1), "=r"(r2), "=r"(r3) : "r"(addr));
}

__device__ __forceinline__ void mma_16816(float* d, const uint32_t* a,
                                          uint32_t b0, uint32_t b1) {
    asm volatile(
        "mma.sync.aligned.m16n8k16.row.col.f32.bf16.bf16.f32 "
        "{%0,%1,%2,%3}, {%4,%5,%6,%7}, {%8,%9}, {%0,%1,%2,%3};"
        : "+f"(d[0]), "+f"(d[1]), "+f"(d[2]), "+f"(d[3])
        : "r"(a[0]), "r"(a[1]), "r"(a[2]), "r"(a[3]), "r"(b0), "r"(b1));
}

// ============================ conversion kernels ===========================
__global__ void convert_x_kernel(const float4* __restrict__ src) {
    size_t i = (size_t)blockIdx.x * blockDim.x + threadIdx.x;
    size_t stride = (size_t)gridDim.x * blockDim.x;
    __nv_bfloat162* dst = reinterpret_cast<__nv_bfloat162*>(g_xb);
    const size_t n4 = (size_t)M * K / 4;
    for (; i < n4; i += stride) {
        float4 v = src[i];
        dst[2 * i]     = __floats2bfloat162_rn(v.x, v.y);
        dst[2 * i + 1] = __floats2bfloat162_rn(v.z, v.w);
    }
}

__global__ void convert_w_kernel(const float4* __restrict__ src) {
    size_t i = (size_t)blockIdx.x * blockDim.x + threadIdx.x;
    size_t stride = (size_t)gridDim.x * blockDim.x;
    __nv_bfloat162* dst = reinterpret_cast<__nv_bfloat162*>(g_wb);
    const size_t n4 = (size_t)N * K / 4;
    for (; i < n4; i += stride) {
        float4 v = src[i];
        dst[2 * i]     = __floats2bfloat162_rn(v.x, v.y);
        dst[2 * i + 1] = __floats2bfloat162_rn(v.z, v.w);
    }
}

// ============================ stage loader =================================
// A tile 128x64 bf16, B tile 256x64 bf16, K-major, 128 B rows,
// 16B-chunk swizzle: chunk c of row r lands at ((c ^ (r & 7)) << 4).
__device__ __forceinline__ void load_stage(uint32_t sb, int s, int kstep,
                                           int m0, int n0, int tid) {
    const int k0 = kstep * TILE_K;
    const uint32_t a_base = sb + SM_A + s * A_BYTES;
    const uint32_t b_base = sb + SM_B + s * B_BYTES;
    const char* xrow = (const char*)(g_xb + (size_t)m0 * K + k0);
    const char* wrow = (const char*)(g_wb + (size_t)n0 * K + k0);
    #pragma unroll
    for (int i = 0; i < 4; i++) {           // A: 1024 chunks / 256 thr
        int idx = tid + i * THREADS;
        int r = idx >> 3, c = idx & 7;
        cp_async16(a_base + r * 128 + ((c ^ (r & 7)) << 4),
                   xrow + (size_t)r * (K * 2) + c * 16);
    }
    #pragma unroll
    for (int i = 0; i < 8; i++) {           // B: 2048 chunks / 256 thr
        int idx = tid + i * THREADS;
        int r = idx >> 3, c = idx & 7;
        cp_async16(b_base + r * 128 + ((c ^ (r & 7)) << 4),
                   wrow + (size_t)r * (K * 2) + c * 16);
    }
}

// ============================ GEMM + fused epilogue ========================
__global__ void __launch_bounds__(THREADS, 1)
gemm_pool_kernel(const float* __restrict__ bias) {
    extern __shared__ char smem[];
    const uint32_t sb = smem_to_u32(smem);
    const int tid  = threadIdx.x;
    const int wid  = tid >> 5;
    const int lane = tid & 31;
    const int wm   = wid >> 2;      // 0..1  (rows: wm*64 .. wm*64+63)
    const int wn   = wid & 3;       // 0..3  (cols: wn*64 .. wn*64+63)
    const int m0 = blockIdx.x * TILE_M;
    const int n0 = blockIdx.y * TILE_N;

    float* bias_s   = reinterpret_cast<float*>(smem + SM_BIAS);
    float* rowsum_s = reinterpret_cast<float*>(smem + SM_ROWSUM); // [4][128]
    for (int i = tid; i < TILE_N; i += THREADS) bias_s[i] = bias[n0 + i];

    // prologue: fill STAGES-1 stages
    #pragma unroll
    for (int s = 0; s < STAGES - 1; s++) {
        load_stage(sb, s, s, m0, n0, tid);
        cp_commit();
    }

    float acc[4][8][4];
    #pragma unroll
    for (int mi = 0; mi < 4; mi++)
        #pragma unroll
        for (int ni = 0; ni < 8; ni++)
            #pragma unroll
            for (int v = 0; v < 4; v++) acc[mi][ni][v] = 0.f;

    for (int ks = 0; ks < KSTEPS; ks++) {
        asm volatile("cp.async.wait_group %0;" :: "n"(STAGES - 2) : "memory");
        __syncthreads();
        if (ks + STAGES - 1 < KSTEPS)
            load_stage(sb, (ks + STAGES - 1) & (STAGES - 1), ks + STAGES - 1,
                       m0, n0, tid);
        cp_commit();   // uniform group accounting

        const int s = ks & (STAGES - 1);
        const uint32_t a_base = sb + SM_A + s * A_BYTES;
        const uint32_t b_base = sb + SM_B + s * B_BYTES;

        #pragma unroll
        for (int kc = 0; kc < 4; kc++) {               // 4 x k16 per stage
            uint32_t a_frag[4][4];
            #pragma unroll
            for (int mi = 0; mi < 4; mi++) {
                int row = wm * 64 + mi * 16 + (lane & 15);
                int ch  = kc * 2 + (lane >> 4);
                ldmatrix_x4(a_frag[mi][0], a_frag[mi][1],
                            a_frag[mi][2], a_frag[mi][3],
                            a_base + row * 128 + ((ch ^ (row & 7)) << 4));
            }
            #pragma unroll
            for (int np = 0; np < 4; np++) {           // 4 x (two n8) = 64 n
                uint32_t b0, b1, b2, b3;
                int row = wn * 64 + np * 16 + (lane & 15);
                int ch  = kc * 2 + (lane >> 4);
                ldmatrix_x4(b0, b1, b2, b3,
                            b_base + row * 128 + ((ch ^ (row & 7)) << 4));
                // ldmatrix reg order: b0=(n0-7,klow) b1=(n8-15,klow)
                //                     b2=(n0-7,khigh) b3=(n8-15,khigh)
                #pragma unroll
                for (int mi = 0; mi < 4; mi++) {
                    mma_16816(acc[mi][np * 2],     a_frag[mi], b0, b2);
                    mma_16816(acc[mi][np * 2 + 1], a_frag[mi], b1, b3);
                }
            }
        }
    }

    // ---- fused epilogue: +bias, maxpool4 (along N), per-row partial sums ----
    // c-frag: c0:(r=l/4, col=2*(l%4)) c1:(r, col+1) c2:(r+8, col) c3:(r+8, col+1)
    float rs[4][2];
    #pragma unroll
    for (int mi = 0; mi < 4; mi++) { rs[mi][0] = 0.f; rs[mi][1] = 0.f; }
    #pragma unroll
    for (int mi = 0; mi < 4; mi++) {
        #pragma unroll
        for (int ni = 0; ni < 8; ni++) {
            int colbase = wn * 64 + ni * 8 + 2 * (lane & 3);
            float bb0 = bias_s[colbase], bb1 = bias_s[colbase + 1];
            float p0 = fmaxf(acc[mi][ni][0] + bb0, acc[mi][ni][1] + bb1);
            float p1 = fmaxf(acc[mi][ni][2] + bb0, acc[mi][ni][3] + bb1);
            float q0 = fmaxf(p0, __shfl_xor_sync(0xffffffffu, p0, 1));
            float q1 = fmaxf(p1, __shfl_xor_sync(0xffffffffu, p1, 1));
            rs[mi][0] += q0 + __shfl_xor_sync(0xffffffffu, q0, 2);
            rs[mi][1] += q1 + __shfl_xor_sync(0xffffffffu, q1, 2);
        }
    }
    // deterministic cross-warp reduce: each wn-warp owns its own slice
    if ((lane & 3) == 0) {
        float* slice = rowsum_s + wn * TILE_M;
        int base = wm * 64 + (lane >> 2);
        #pragma unroll
        for (int mi = 0; mi < 4; mi++) {
            slice[base + mi * 16]     = rs[mi][0];
            slice[base + mi * 16 + 8] = rs[mi][1];
        }
    }
    __syncthreads();
    if (tid < TILE_M) {
        float v = (rowsum_s[tid] + rowsum_s[TILE_M + tid]) +
                  (rowsum_s[2 * TILE_M + tid] + rowsum_s[3 * TILE_M + tid]);
        g_part[(size_t)blockIdx.y * M + m0 + tid] = v;
    }
}

// ============================ final reduce =================================
__global__ void reduce_kernel(float* __restrict__ out) {
    int m = blockIdx.x * blockDim.x + threadIdx.x;
    if (m < M) {
        float s = 0.f;
        #pragma unroll
        for (int t = 0; t < N_TILES; t++) s += g_part[(size_t)t * M + m];
        out[m] = s * 0.5f;
    }
}

// ============================ launch =======================================
extern "C" void kernel_launch(void* const* d_in, const int* in_sizes, int n_in,
                              void* d_out, int out_size) {
    const float* x    = (const float*)d_in[0];
    const float* w    = (const float*)d_in[1];
    const float* bias = (const float*)d_in[2];
    float* out = (float*)d_out;

    convert_x_kernel<<<2048, 256>>>((const float4*)x);
    convert_w_kernel<<<1024, 256>>>((const float4*)w);

    cudaFuncSetAttribute(gemm_pool_kernel,
                         cudaFuncAttributeMaxDynamicSharedMemorySize, SMEM_TOTAL);
    gemm_pool_kernel<<<dim3(M_TILES, N_TILES), THREADS, SMEM_TOTAL>>>(bias);

    reduce_kernel<<<(M + 255) / 256, 256>>>(out);
}

// round 5
// speedup vs baseline: 1.1080x; 1.1080x over previous
#include <cuda_runtime.h>
#include <cuda_bf16.h>
#include <cstdint>

// ============================ problem constants ============================
constexpr int M = 16384;
constexpr int N = 4096;
constexpr int K = 1024;

constexpr int TILE_M = 128;
constexpr int TILE_N = 128;
constexpr int TILE_K = 64;               // 64 bf16 = 128 B rows
constexpr int KSTEPS = K / TILE_K;       // 16
constexpr int STAGES = 3;
constexpr int M_TILES = M / TILE_M;      // 128
constexpr int N_TILES = N / TILE_N;      // 32
constexpr int THREADS = 256;             // 8 warps: 2(m) x 4(n), warp tile 64x32

// ============================ device scratch ===============================
__device__ __nv_bfloat16 g_xb[(size_t)M * K];          // 32 MB
__device__ __nv_bfloat16 g_wb[(size_t)N * K];          //  8 MB
__device__ float         g_part[(size_t)N_TILES * M];  //  2 MB

// ============================ smem layout (bytes) ==========================
constexpr int SM_BIAS   = 0;                         // 128 floats = 512 B
constexpr int SM_ROWSUM = 512;                       // 4 x 128 floats = 2048 B
constexpr int A_BYTES   = TILE_M * 128;              // 16384
constexpr int B_BYTES   = TILE_N * 128;              // 16384
constexpr int SM_A      = 4096;
constexpr int SM_B      = SM_A + STAGES * A_BYTES;   // 53248
constexpr int SMEM_TOTAL = SM_B + STAGES * B_BYTES;  // 102400 (100 KB) -> 2 CTAs/SM

// ============================ PTX helpers ==================================
__device__ __forceinline__ uint32_t smem_to_u32(const void* p) {
    uint32_t a;
    asm("{ .reg .u64 t; cvta.to.shared.u64 t, %1; cvt.u32.u64 %0, t; }"
        : "=r"(a) : "l"(p));
    return a;
}

__device__ __forceinline__ void cp_async16(uint32_t smem_dst, const void* gsrc) {
    asm volatile("cp.async.cg.shared.global [%0], [%1], 16;"
                 :: "r"(smem_dst), "l"(gsrc) : "memory");
}

__device__ __forceinline__ void cp_commit() {
    asm volatile("cp.async.commit_group;" ::: "memory");
}

__device__ __forceinline__ void ldmatrix_x4(uint32_t& r0, uint32_t& r1,
                                            uint32_t& r2, uint32_t& r3,
                                            uint32_t addr) {
    asm volatile("ldmatrix.sync.aligned.m8n8.x4.shared.b16 {%0,%1,%2,%3}, [%4];"
                 : "=r"(r0), "=r"(r1), "=r"(r2), "=r"(r3) : "r"(addr));
}

__device__ __forceinline__ void mma_16816(float* d, const uint32_t* a,
                                          uint32_t b0, uint32_t b1) {
    asm volatile(
        "mma.sync.aligned.m16n8k16.row.col.f32.bf16.bf16.f32 "
        "{%0,%1,%2,%3}, {%4,%5,%6,%7}, {%8,%9}, {%0,%1,%2,%3};"
        : "+f"(d[0]), "+f"(d[1]), "+f"(d[2]), "+f"(d[3])
        : "r"(a[0]), "r"(a[1]), "r"(a[2]), "r"(a[3]), "r"(b0), "r"(b1));
}

// ============================ conversion kernels ===========================
__global__ void convert_x_kernel(const float4* __restrict__ src) {
    size_t i = (size_t)blockIdx.x * blockDim.x + threadIdx.x;
    size_t stride = (size_t)gridDim.x * blockDim.x;
    __nv_bfloat162* dst = reinterpret_cast<__nv_bfloat162*>(g_xb);
    const size_t n4 = (size_t)M * K / 4;
    for (; i < n4; i += stride) {
        float4 v = src[i];
        dst[2 * i]     = __floats2bfloat162_rn(v.x, v.y);
        dst[2 * i + 1] = __floats2bfloat162_rn(v.z, v.w);
    }
}

__global__ void convert_w_kernel(const float4* __restrict__ src) {
    size_t i = (size_t)blockIdx.x * blockDim.x + threadIdx.x;
    size_t stride = (size_t)gridDim.x * blockDim.x;
    __nv_bfloat162* dst = reinterpret_cast<__nv_bfloat162*>(g_wb);
    const size_t n4 = (size_t)N * K / 4;
    for (; i < n4; i += stride) {
        float4 v = src[i];
        dst[2 * i]     = __floats2bfloat162_rn(v.x, v.y);
        dst[2 * i + 1] = __floats2bfloat162_rn(v.z, v.w);
    }
}

// ============================ stage loader =================================
// A tile 128x64 bf16, B tile 128x64 bf16, K-major, 128 B rows,
// 16B-chunk swizzle: chunk c of row r lands at ((c ^ (r & 7)) << 4).
__device__ __forceinline__ void load_stage(uint32_t sb, int s, int kstep,
                                           int m0, int n0, int tid) {
    const int k0 = kstep * TILE_K;
    const uint32_t a_base = sb + SM_A + s * A_BYTES;
    const uint32_t b_base = sb + SM_B + s * B_BYTES;
    const char* xrow = (const char*)(g_xb + (size_t)m0 * K + k0);
    const char* wrow = (const char*)(g_wb + (size_t)n0 * K + k0);
    #pragma unroll
    for (int i = 0; i < 4; i++) {           // A: 1024 chunks / 256 thr
        int idx = tid + i * THREADS;
        int r = idx >> 3, c = idx & 7;
        cp_async16(a_base + r * 128 + ((c ^ (r & 7)) << 4),
                   xrow + (size_t)r * (K * 2) + c * 16);
    }
    #pragma unroll
    for (int i = 0; i < 4; i++) {           // B: 1024 chunks / 256 thr
        int idx = tid + i * THREADS;
        int r = idx >> 3, c = idx & 7;
        cp_async16(b_base + r * 128 + ((c ^ (r & 7)) << 4),
                   wrow + (size_t)r * (K * 2) + c * 16);
    }
}

// ============================ GEMM + fused epilogue ========================
__global__ void __launch_bounds__(THREADS, 2)
gemm_pool_kernel(const float* __restrict__ bias) {
    extern __shared__ char smem[];
    const uint32_t sb = smem_to_u32(smem);
    const int tid  = threadIdx.x;
    const int wid  = tid >> 5;
    const int lane = tid & 31;
    const int wm   = wid >> 2;      // 0..1  (rows: wm*64 .. wm*64+63)
    const int wn   = wid & 3;       // 0..3  (cols: wn*32 .. wn*32+31)
    const int m0 = blockIdx.x * TILE_M;
    const int n0 = blockIdx.y * TILE_N;

    float* bias_s   = reinterpret_cast<float*>(smem + SM_BIAS);
    float* rowsum_s = reinterpret_cast<float*>(smem + SM_ROWSUM); // [4][128]
    for (int i = tid; i < TILE_N; i += THREADS) bias_s[i] = bias[n0 + i];

    // prologue: fill STAGES-1 stages
    #pragma unroll
    for (int s = 0; s < STAGES - 1; s++) {
        load_stage(sb, s, s, m0, n0, tid);
        cp_commit();
    }

    float acc[4][4][4];
    #pragma unroll
    for (int mi = 0; mi < 4; mi++)
        #pragma unroll
        for (int ni = 0; ni < 4; ni++)
            #pragma unroll
            for (int v = 0; v < 4; v++) acc[mi][ni][v] = 0.f;

    int s_cur = 0, s_nxt = STAGES - 1;
    for (int ks = 0; ks < KSTEPS; ks++) {
        asm volatile("cp.async.wait_group %0;" :: "n"(STAGES - 2) : "memory");
        __syncthreads();
        if (ks + STAGES - 1 < KSTEPS)
            load_stage(sb, s_nxt, ks + STAGES - 1, m0, n0, tid);
        cp_commit();   // uniform group accounting

        const uint32_t a_base = sb + SM_A + s_cur * A_BYTES;
        const uint32_t b_base = sb + SM_B + s_cur * B_BYTES;

        #pragma unroll
        for (int kc = 0; kc < 4; kc++) {               // 4 x k16 per stage
            uint32_t a_frag[4][4];
            #pragma unroll
            for (int mi = 0; mi < 4; mi++) {
                int row = wm * 64 + mi * 16 + (lane & 15);
                int ch  = kc * 2 + (lane >> 4);
                ldmatrix_x4(a_frag[mi][0], a_frag[mi][1],
                            a_frag[mi][2], a_frag[mi][3],
                            a_base + row * 128 + ((ch ^ (row & 7)) << 4));
            }
            #pragma unroll
            for (int np = 0; np < 2; np++) {           // 2 x (two n8) = 32 n
                uint32_t b0, b1, b2, b3;
                int row = wn * 32 + np * 16 + (lane & 15);
                int ch  = kc * 2 + (lane >> 4);
                ldmatrix_x4(b0, b1, b2, b3,
                            b_base + row * 128 + ((ch ^ (row & 7)) << 4));
                // reg order: b0=(n0-7,klow) b1=(n8-15,klow)
                //            b2=(n0-7,khigh) b3=(n8-15,khigh)
                #pragma unroll
                for (int mi = 0; mi < 4; mi++) {
                    mma_16816(acc[mi][np * 2],     a_frag[mi], b0, b2);
                    mma_16816(acc[mi][np * 2 + 1], a_frag[mi], b1, b3);
                }
            }
        }
        s_cur++; if (s_cur == STAGES) s_cur = 0;
        s_nxt++; if (s_nxt == STAGES) s_nxt = 0;
    }

    // ---- fused epilogue: +bias, maxpool4 (along N), per-row partial sums ----
    // c-frag: c0:(r=l/4, col=2*(l%4)) c1:(r, col+1) c2:(r+8, col) c3:(r+8, col+1)
    float rs[4][2];
    #pragma unroll
    for (int mi = 0; mi < 4; mi++) { rs[mi][0] = 0.f; rs[mi][1] = 0.f; }
    #pragma unroll
    for (int mi = 0; mi < 4; mi++) {
        #pragma unroll
        for (int ni = 0; ni < 4; ni++) {
            int colbase = wn * 32 + ni * 8 + 2 * (lane & 3);
            float bb0 = bias_s[colbase], bb1 = bias_s[colbase + 1];
            float p0 = fmaxf(acc[mi][ni][0] + bb0, acc[mi][ni][1] + bb1);
            float p1 = fmaxf(acc[mi][ni][2] + bb0, acc[mi][ni][3] + bb1);
            float q0 = fmaxf(p0, __shfl_xor_sync(0xffffffffu, p0, 1));
            float q1 = fmaxf(p1, __shfl_xor_sync(0xffffffffu, p1, 1));
            rs[mi][0] += q0 + __shfl_xor_sync(0xffffffffu, q0, 2);
            rs[mi][1] += q1 + __shfl_xor_sync(0xffffffffu, q1, 2);
        }
    }
    // deterministic cross-warp reduce: each wn-warp owns its own slice
    if ((lane & 3) == 0) {
        float* slice = rowsum_s + wn * TILE_M;
        int base = wm * 64 + (lane >> 2);
        #pragma unroll
        for (int mi = 0; mi < 4; mi++) {
            slice[base + mi * 16]     = rs[mi][0];
            slice[base + mi * 16 + 8] = rs[mi][1];
        }
    }
    __syncthreads();
    if (tid < TILE_M) {
        float v = (rowsum_s[tid] + rowsum_s[TILE_M + tid]) +
                  (rowsum_s[2 * TILE_M + tid] + rowsum_s[3 * TILE_M + tid]);
        g_part[(size_t)blockIdx.y * M + m0 + tid] = v;
    }
}

// ============================ final reduce =================================
__global__ void reduce_kernel(float* __restrict__ out) {
    int m = blockIdx.x * blockDim.x + threadIdx.x;
    if (m < M) {
        float s = 0.f;
        #pragma unroll
        for (int t = 0; t < N_TILES; t++) s += g_part[(size_t)t * M + m];
        out[m] = s * 0.5f;
    }
}

// ============================ launch =======================================
extern "C" void kernel_launch(void* const* d_in, const int* in_sizes, int n_in,
                              void* d_out, int out_size) {
    const float* x    = (const float*)d_in[0];
    const float* w    = (const float*)d_in[1];
    const float* bias = (const float*)d_in[2];
    float* out = (float*)d_out;

    convert_x_kernel<<<2048, 256>>>((const float4*)x);
    convert_w_kernel<<<1024, 256>>>((const float4*)w);

    cudaFuncSetAttribute(gemm_pool_kernel,
                         cudaFuncAttributeMaxDynamicSharedMemorySize, SMEM_TOTAL);
    gemm_pool_kernel<<<dim3(M_TILES, N_TILES), THREADS, SMEM_TOTAL>>>(bias);

    reduce_kernel<<<(M + 255) / 256, 256>>>(out);
}